// round 7
// baseline (speedup 1.0000x reference)
#include <cuda_runtime.h>
#include <cstdint>

#define NB   2
#define CIN  128
#define CH   64
#define NPOS 4096
#define JB   128          // 32-wide stat blocks
#define ASPLIT 8

typedef uint32_t u32;

// ================= helpers =================
__device__ __forceinline__ float to_tf32(float x) {
    float r; asm("cvt.rna.tf32.f32 %0, %1;" : "=f"(r) : "f"(x)); return r;
}
__device__ __forceinline__ void mma_tf32(float c[4], u32 a0, u32 a1, u32 a2, u32 a3,
                                         u32 b0, u32 b1) {
    asm volatile("mma.sync.aligned.m16n8k8.row.col.f32.tf32.tf32.f32 "
                 "{%0,%1,%2,%3}, {%4,%5,%6,%7}, {%8,%9}, {%0,%1,%2,%3};"
                 : "+f"(c[0]), "+f"(c[1]), "+f"(c[2]), "+f"(c[3])
                 : "r"(a0), "r"(a1), "r"(a2), "r"(a3), "r"(b0), "r"(b1));
}
__device__ __forceinline__ u32 fu(float x) { return __float_as_uint(x); }

// ================= scratch =================
__device__ float g_kT_hi[NB * NPOS * CH];   // [b][i][c]
__device__ float g_kT_lo[NB * NPOS * CH];
__device__ float g_qT_hi[NB * NPOS * CH];   // [b][j][c]
__device__ float g_qT_lo[NB * NPOS * CH];
__device__ float g_v_hi[NB * CH * NPOS];    // [b][c][i]
__device__ float g_v_lo[NB * CH * NPOS];
__device__ float g_S [(size_t)NB * NPOS * NPOS];
__device__ float g_mpart[NB * JB * NPOS];
__device__ float g_spart[NB * JB * NPOS];
__device__ float g_m[NB * NPOS];
__device__ float g_w[NB * NPOS];
__device__ float g_aggp[ASPLIT][NB * CH * NPOS];
__device__ float g_agg[NB * CH * NPOS];

// ================= K1: qkv (pre-split tf32 hi/lo) =================
__global__ void __launch_bounds__(128) qkv_kernel(
    const float* __restrict__ x,
    const float* __restrict__ Wq,
    const float* __restrict__ Wk,
    const float* __restrict__ Wv)
{
    int b   = blockIdx.x;
    int pos = blockIdx.y * 128 + threadIdx.x;
    int z   = blockIdx.z;            // 0..23
    int mat = z >> 3;
    int o0  = (z & 7) * 8;
    const float* W = (mat == 0) ? Wq : (mat == 1) ? Wk : Wv;

    float acc[8];
#pragma unroll
    for (int u = 0; u < 8; u++) acc[u] = 0.f;
    const float* xp = x + (size_t)b * CIN * NPOS + pos;
#pragma unroll 4
    for (int c = 0; c < CIN; c++) {
        float xv = xp[(size_t)c * NPOS];
#pragma unroll
        for (int u = 0; u < 8; u++)
            acc[u] += W[(o0 + u) * CIN + c] * xv;
    }
    if (mat == 2) {
#pragma unroll
        for (int u = 0; u < 8; u++) {
            float h = to_tf32(acc[u]);
            float l = to_tf32(acc[u] - h);
            size_t o = ((size_t)b * CH + o0 + u) * NPOS + pos;
            g_v_hi[o] = h;
            g_v_lo[o] = l;
        }
    } else {
        float* hi = (mat == 0) ? g_qT_hi : g_kT_hi;
        float* lo = (mat == 0) ? g_qT_lo : g_kT_lo;
        size_t base = ((size_t)b * NPOS + pos) * CH + o0;
        float h[8], l[8];
#pragma unroll
        for (int u = 0; u < 8; u++) {
            h[u] = to_tf32(acc[u]);
            l[u] = to_tf32(acc[u] - h[u]);
        }
        *(float4*)&hi[base]     = make_float4(h[0], h[1], h[2], h[3]);
        *(float4*)&hi[base + 4] = make_float4(h[4], h[5], h[6], h[7]);
        *(float4*)&lo[base]     = make_float4(l[0], l[1], l[2], l[3]);
        *(float4*)&lo[base + 4] = make_float4(l[4], l[5], l[6], l[7]);
    }
}

// ================= K2: scores via mma.sync tf32 (3x split, pre-split) =================
// grid (32 jt, 32 it, NB), block 256 (8 warps: 2 i x 4 j).
#define ST 68
#define SC_KHI 0
#define SC_KLO (128 * ST)
#define SC_QHI (2 * 128 * ST)
#define SC_QLO (3 * 128 * ST)
#define SC_SMEM (4 * 128 * ST * 4)
__global__ void __launch_bounds__(256) scores_kernel()
{
    extern __shared__ float sm[];
    float* sKhi = sm + SC_KHI;
    float* sKlo = sm + SC_KLO;
    float* sQhi = sm + SC_QHI;
    float* sQlo = sm + SC_QLO;

    int b  = blockIdx.z;
    int i0 = blockIdx.y * 128;
    int j0 = blockIdx.x * 128;
    int tid = threadIdx.x, wid = tid >> 5, lane = tid & 31;
    int gid = lane >> 2, ctid = lane & 3;
    int warp_i = wid >> 2;                 // 0..1
    int warp_j = wid & 3;                  // 0..3
    int ibase = warp_i * 64, jbase = warp_j * 32;

    // stage 4 tiles (128 rows x 64 c each), float4 coalesced
    {
        const float4* khi = (const float4*)(g_kT_hi + ((size_t)b * NPOS + i0) * CH);
        const float4* klo = (const float4*)(g_kT_lo + ((size_t)b * NPOS + i0) * CH);
        const float4* qhi = (const float4*)(g_qT_hi + ((size_t)b * NPOS + j0) * CH);
        const float4* qlo = (const float4*)(g_qT_lo + ((size_t)b * NPOS + j0) * CH);
        for (int idx = tid; idx < 2048; idx += 256) {
            int row = idx >> 4, c4 = (idx & 15) * 4;
            *(float4*)&sKhi[row * ST + c4] = khi[idx];
            *(float4*)&sKlo[row * ST + c4] = klo[idx];
            *(float4*)&sQhi[row * ST + c4] = qhi[idx];
            *(float4*)&sQlo[row * ST + c4] = qlo[idx];
        }
    }
    __syncthreads();

    float cfr[4][4][4];
#pragma unroll
    for (int ti = 0; ti < 4; ti++)
#pragma unroll
        for (int tj = 0; tj < 4; tj++)
#pragma unroll
            for (int r = 0; r < 4; r++) cfr[ti][tj][r] = 0.f;

#pragma unroll
    for (int ks = 0; ks < 8; ks++) {
        int k = ks * 8 + ctid;
        u32 ahi[4][4], alo[4][4];
#pragma unroll
        for (int ti = 0; ti < 4; ti++) {
            int r0 = (ibase + ti * 16 + gid) * ST + k;
            int r1 = r0 + 8 * ST;
            ahi[ti][0] = fu(sKhi[r0]);     ahi[ti][1] = fu(sKhi[r1]);
            ahi[ti][2] = fu(sKhi[r0 + 4]); ahi[ti][3] = fu(sKhi[r1 + 4]);
            alo[ti][0] = fu(sKlo[r0]);     alo[ti][1] = fu(sKlo[r1]);
            alo[ti][2] = fu(sKlo[r0 + 4]); alo[ti][3] = fu(sKlo[r1 + 4]);
        }
        u32 bhi[4][2], blo[4][2];
#pragma unroll
        for (int tj = 0; tj < 4; tj++) {
            int c0 = (jbase + tj * 8 + gid) * ST + k;
            bhi[tj][0] = fu(sQhi[c0]); bhi[tj][1] = fu(sQhi[c0 + 4]);
            blo[tj][0] = fu(sQlo[c0]); blo[tj][1] = fu(sQlo[c0 + 4]);
        }
#pragma unroll
        for (int ti = 0; ti < 4; ti++)
#pragma unroll
            for (int tj = 0; tj < 4; tj++) {
                mma_tf32(cfr[ti][tj], ahi[ti][0], ahi[ti][1], ahi[ti][2], ahi[ti][3],
                         bhi[tj][0], bhi[tj][1]);
                mma_tf32(cfr[ti][tj], ahi[ti][0], ahi[ti][1], ahi[ti][2], ahi[ti][3],
                         blo[tj][0], blo[tj][1]);
                mma_tf32(cfr[ti][tj], alo[ti][0], alo[ti][1], alo[ti][2], alo[ti][3],
                         bhi[tj][0], bhi[tj][1]);
            }
    }

    // ---- write S (float2, sector-coalesced) ----
    float* Sb = g_S + (size_t)b * NPOS * NPOS;
#pragma unroll
    for (int ti = 0; ti < 4; ti++) {
        int row0 = i0 + ibase + ti * 16 + gid;
#pragma unroll
        for (int tj = 0; tj < 4; tj++) {
            int col = j0 + jbase + tj * 8 + 2 * ctid;
            *(float2*)&Sb[(size_t)row0 * NPOS + col] =
                make_float2(cfr[ti][tj][0], cfr[ti][tj][1]);
            *(float2*)&Sb[(size_t)(row0 + 8) * NPOS + col] =
                make_float2(cfr[ti][tj][2], cfr[ti][tj][3]);
        }
    }

    // ---- stats over this warp's 32 j-cols ----
    int jb = blockIdx.x * 4 + warp_j;
#pragma unroll
    for (int ti = 0; ti < 4; ti++) {
        float m0 = -1e30f, m1 = -1e30f;
#pragma unroll
        for (int tj = 0; tj < 4; tj++) {
            m0 = fmaxf(m0, fmaxf(cfr[ti][tj][0], cfr[ti][tj][1]));
            m1 = fmaxf(m1, fmaxf(cfr[ti][tj][2], cfr[ti][tj][3]));
        }
#pragma unroll
        for (int o = 1; o < 4; o <<= 1) {
            m0 = fmaxf(m0, __shfl_xor_sync(0xffffffffu, m0, o));
            m1 = fmaxf(m1, __shfl_xor_sync(0xffffffffu, m1, o));
        }
        float s0 = 0.f, s1 = 0.f;
#pragma unroll
        for (int tj = 0; tj < 4; tj++) {
            s0 += __expf(cfr[ti][tj][0] - m0) + __expf(cfr[ti][tj][1] - m0);
            s1 += __expf(cfr[ti][tj][2] - m1) + __expf(cfr[ti][tj][3] - m1);
        }
#pragma unroll
        for (int o = 1; o < 4; o <<= 1) {
            s0 += __shfl_xor_sync(0xffffffffu, s0, o);
            s1 += __shfl_xor_sync(0xffffffffu, s1, o);
        }
        if (ctid == 0) {
            int row = i0 + ibase + ti * 16 + gid;
            size_t sbase = ((size_t)b * JB + jb) * NPOS;
            g_mpart[sbase + row]     = m0;
            g_spart[sbase + row]     = s0;
            g_mpart[sbase + row + 8] = m1;
            g_spart[sbase + row + 8] = s1;
        }
    }
}

// ================= K3: combine stats =================
__global__ void __launch_bounds__(256) combine_kernel()
{
    int e = blockIdx.x * 256 + threadIdx.x;
    if (e >= NB * NPOS) return;
    int b = e / NPOS, i = e % NPOS;
    const float* mp = g_mpart + (size_t)b * JB * NPOS + i;
    const float* sp = g_spart + (size_t)b * JB * NPOS + i;
    float m = -1e30f;
#pragma unroll 8
    for (int jb = 0; jb < JB; jb++) m = fmaxf(m, mp[(size_t)jb * NPOS]);
    float s = 0.f;
#pragma unroll 8
    for (int jb = 0; jb < JB; jb++)
        s += __expf(mp[(size_t)jb * NPOS] - m) * sp[(size_t)jb * NPOS];
    g_m[e] = m;
    g_w[e] = 1.f / s;
}

// ================= K4: agg via mma.sync tf32, 2-pass, exp inline =================
// out[c][j] = sum_i v[c][i] * P[i][j];  M=64 c, N=128 j, K=i chunks of 64.
// grid (32 jt, ASPLIT, NB), block 256 (8 warps: 2 c x 4 j).
#define AG_VS 68
#define AG_PS 136
#define AG_VLO (64 * AG_VS)
#define AG_P   (2 * 64 * AG_VS)
#define AG_M   (2 * 64 * AG_VS + 64 * AG_PS)
#define AG_W   (AG_M + 64)
#define AG_SMEM ((AG_W + 64) * 4)
__global__ void __launch_bounds__(256) agg_kernel()
{
    extern __shared__ float sm[];
    float* sVhi = sm;
    float* sVlo = sm + AG_VLO;
    float* sP   = sm + AG_P;        // [64 i][136], tf32-rounded
    float* sM   = sm + AG_M;
    float* sW   = sm + AG_W;

    int b  = blockIdx.z;
    int ks = blockIdx.y;
    int j0 = blockIdx.x * 128;
    const int IRANGE = NPOS / ASPLIT;       // 512
    int ibase_g = ks * IRANGE;

    int tid = threadIdx.x, wid = tid >> 5, lane = tid & 31;
    int gid = lane >> 2, ctid = lane & 3;
    int warp_c = wid >> 2;                  // 0..1
    int warp_j = wid & 3;                   // 0..3
    int cbase = warp_c * 32, jbase = warp_j * 32;

    const float* vhi = g_v_hi + (size_t)b * CH * NPOS;
    const float* vlo = g_v_lo + (size_t)b * CH * NPOS;
    const float* Sb  = g_S + (size_t)b * NPOS * NPOS;

    float cfr[2][4][4];
#pragma unroll
    for (int ti = 0; ti < 2; ti++)
#pragma unroll
        for (int tj = 0; tj < 4; tj++)
#pragma unroll
            for (int r = 0; r < 4; r++) cfr[ti][tj][r] = 0.f;

#pragma unroll 1
    for (int ck = 0; ck < IRANGE / 64; ck++) {
        int i0 = ibase_g + ck * 64;
        __syncthreads();
        if (tid < 64) {
            sM[tid] = g_m[b * NPOS + i0 + tid];
            sW[tid] = g_w[b * NPOS + i0 + tid];
        }
        // stage V hi/lo [64 c][64 i]
        for (int idx = tid; idx < 1024; idx += 256) {
            int c = idx >> 4, i4 = (idx & 15) * 4;
            *(float4*)&sVhi[c * AG_VS + i4] =
                *(const float4*)&vhi[(size_t)c * NPOS + i0 + i4];
            *(float4*)&sVlo[c * AG_VS + i4] =
                *(const float4*)&vlo[(size_t)c * NPOS + i0 + i4];
        }
        __syncthreads();    // sM/sW visible
        // stage P [64 i][128 j], exp + tf32-round inline
        for (int idx = tid; idx < 1024; idx += 256) {
            int ii = idx >> 4, jj4 = (idx & 15) * 8;
            float4 s0 = *(const float4*)&Sb[(size_t)(i0 + ii) * NPOS + j0 + jj4];
            float4 s1 = *(const float4*)&Sb[(size_t)(i0 + ii) * NPOS + j0 + jj4 + 4];
            float m = sM[ii], w = sW[ii];
            float4 p0 = make_float4(to_tf32(__expf(s0.x - m) * w), to_tf32(__expf(s0.y - m) * w),
                                    to_tf32(__expf(s0.z - m) * w), to_tf32(__expf(s0.w - m) * w));
            float4 p1 = make_float4(to_tf32(__expf(s1.x - m) * w), to_tf32(__expf(s1.y - m) * w),
                                    to_tf32(__expf(s1.z - m) * w), to_tf32(__expf(s1.w - m) * w));
            *(float4*)&sP[ii * AG_PS + jj4]     = p0;
            *(float4*)&sP[ii * AG_PS + jj4 + 4] = p1;
        }
        __syncthreads();

#pragma unroll
        for (int kk = 0; kk < 8; kk++) {
            int k = kk * 8 + ctid;
            u32 ahi[2][4], alo[2][4];
#pragma unroll
            for (int ti = 0; ti < 2; ti++) {
                int r0 = (cbase + ti * 16 + gid) * AG_VS + k;
                int r1 = r0 + 8 * AG_VS;
                ahi[ti][0] = fu(sVhi[r0]);     ahi[ti][1] = fu(sVhi[r1]);
                ahi[ti][2] = fu(sVhi[r0 + 4]); ahi[ti][3] = fu(sVhi[r1 + 4]);
                alo[ti][0] = fu(sVlo[r0]);     alo[ti][1] = fu(sVlo[r1]);
                alo[ti][2] = fu(sVlo[r0 + 4]); alo[ti][3] = fu(sVlo[r1 + 4]);
            }
            u32 bb[4][2];
#pragma unroll
            for (int tj = 0; tj < 4; tj++) {
                int col = jbase + tj * 8 + gid;
                bb[tj][0] = fu(sP[k * AG_PS + col]);
                bb[tj][1] = fu(sP[(k + 4) * AG_PS + col]);
            }
#pragma unroll
            for (int ti = 0; ti < 2; ti++)
#pragma unroll
                for (int tj = 0; tj < 4; tj++) {
                    mma_tf32(cfr[ti][tj], ahi[ti][0], ahi[ti][1], ahi[ti][2], ahi[ti][3],
                             bb[tj][0], bb[tj][1]);
                    mma_tf32(cfr[ti][tj], alo[ti][0], alo[ti][1], alo[ti][2], alo[ti][3],
                             bb[tj][0], bb[tj][1]);
                }
        }
    }

    float* ap = g_aggp[ks] + (size_t)b * CH * NPOS;
#pragma unroll
    for (int ti = 0; ti < 2; ti++) {
        int c0 = cbase + ti * 16 + gid;
#pragma unroll
        for (int tj = 0; tj < 4; tj++) {
            int col = j0 + jbase + tj * 8 + 2 * ctid;
            *(float2*)&ap[(size_t)c0 * NPOS + col] =
                make_float2(cfr[ti][tj][0], cfr[ti][tj][1]);
            *(float2*)&ap[(size_t)(c0 + 8) * NPOS + col] =
                make_float2(cfr[ti][tj][2], cfr[ti][tj][3]);
        }
    }
}

// ================= K4b: reduce split-K partials =================
__global__ void __launch_bounds__(256) agg_reduce_kernel()
{
    int e = blockIdx.x * 256 + threadIdx.x;
    if (e >= NB * CH * NPOS) return;
    float s = 0.f;
#pragma unroll
    for (int ks = 0; ks < ASPLIT; ks++) s += g_aggp[ks][e];
    g_agg[e] = s;
}

// ================= K5: out = Wpost * agg + x =================
__global__ void __launch_bounds__(128) post_kernel(
    const float* __restrict__ x,
    const float* __restrict__ Wpost,
    float* __restrict__ out)
{
    int b   = blockIdx.x;
    int pos = blockIdx.y * 128 + threadIdx.x;
    int o0  = blockIdx.z * 8;

    float acc[8];
#pragma unroll
    for (int u = 0; u < 8; u++) acc[u] = 0.f;
    const float* ap = g_agg + (size_t)b * CH * NPOS + pos;
#pragma unroll 4
    for (int c = 0; c < CH; c++) {
        float av = ap[(size_t)c * NPOS];
#pragma unroll
        for (int u = 0; u < 8; u++)
            acc[u] += Wpost[(o0 + u) * CH + c] * av;
    }
#pragma unroll
    for (int u = 0; u < 8; u++) {
        size_t o = ((size_t)b * CIN + o0 + u) * NPOS + pos;
        out[o] = acc[u] + x[o];
    }
}

// ================= launch =================
extern "C" void kernel_launch(void* const* d_in, const int* in_sizes, int n_in,
                              void* d_out, int out_size)
{
    const float* x     = (const float*)d_in[0];
    const float* Wq    = (const float*)d_in[1];
    const float* Wk    = (const float*)d_in[2];
    const float* Wv    = (const float*)d_in[3];
    const float* Wpost = (const float*)d_in[4];
    float* out = (float*)d_out;

    cudaFuncSetAttribute(scores_kernel, cudaFuncAttributeMaxDynamicSharedMemorySize, SC_SMEM);
    cudaFuncSetAttribute(agg_kernel,    cudaFuncAttributeMaxDynamicSharedMemorySize, AG_SMEM);

    qkv_kernel<<<dim3(NB, NPOS / 128, 24), 128>>>(x, Wq, Wk, Wv);
    scores_kernel<<<dim3(NPOS / 128, NPOS / 128, NB), 256, SC_SMEM>>>();
    combine_kernel<<<(NB * NPOS + 255) / 256, 256>>>();
    agg_kernel<<<dim3(NPOS / 128, ASPLIT, NB), 256, AG_SMEM>>>();
    agg_reduce_kernel<<<(NB * CH * NPOS + 255) / 256, 256>>>();
    post_kernel<<<dim3(NB, NPOS / 128, 16), 128>>>(x, Wpost, out);
}

// round 8
// speedup vs baseline: 1.5469x; 1.5469x over previous
#include <cuda_runtime.h>
#include <cuda_fp16.h>
#include <cstdint>

#define NB   2
#define CIN  128
#define CH   64
#define NPOS 4096
#define JB   128          // 32-wide stat blocks
#define ASPLIT 8

typedef uint32_t u32;

// ================= helpers =================
__device__ __forceinline__ void mma_f16(float c[4], u32 a0, u32 a1, u32 a2, u32 a3,
                                        u32 b0, u32 b1) {
    asm volatile("mma.sync.aligned.m16n8k16.row.col.f32.f16.f16.f32 "
                 "{%0,%1,%2,%3}, {%4,%5,%6,%7}, {%8,%9}, {%0,%1,%2,%3};"
                 : "+f"(c[0]), "+f"(c[1]), "+f"(c[2]), "+f"(c[3])
                 : "r"(a0), "r"(a1), "r"(a2), "r"(a3), "r"(b0), "r"(b1));
}

// ================= scratch =================
__device__ __half g_kh[NB * NPOS * CH];     // [b][i][c]
__device__ __half g_kl[NB * NPOS * CH];
__device__ __half g_qh[NB * NPOS * CH];     // [b][j][c]
__device__ __half g_ql[NB * NPOS * CH];
__device__ __half g_vh[NB * CH * NPOS];     // [b][c][i]
__device__ __half g_vl[NB * CH * NPOS];
__device__ __half g_P [(size_t)NB * NPOS * NPOS];   // P_loc = exp(S - m_block), 67MB
__device__ float g_mpart[NB * JB * NPOS];
__device__ float g_spart[NB * JB * NPOS];
__device__ float g_m[NB * NPOS];
__device__ float g_w[NB * NPOS];
__device__ float g_aggp[ASPLIT][NB * CH * NPOS];
__device__ float g_agg[NB * CH * NPOS];

// ================= K1: qkv (fp16 hi/lo split) =================
__global__ void __launch_bounds__(128) qkv_kernel(
    const float* __restrict__ x,
    const float* __restrict__ Wq,
    const float* __restrict__ Wk,
    const float* __restrict__ Wv)
{
    int b   = blockIdx.x;
    int pos = blockIdx.y * 128 + threadIdx.x;
    int z   = blockIdx.z;            // 0..23
    int mat = z >> 3;
    int o0  = (z & 7) * 8;
    const float* W = (mat == 0) ? Wq : (mat == 1) ? Wk : Wv;

    float acc[8];
#pragma unroll
    for (int u = 0; u < 8; u++) acc[u] = 0.f;
    const float* xp = x + (size_t)b * CIN * NPOS + pos;
#pragma unroll 4
    for (int c = 0; c < CIN; c++) {
        float xv = xp[(size_t)c * NPOS];
#pragma unroll
        for (int u = 0; u < 8; u++)
            acc[u] += W[(o0 + u) * CIN + c] * xv;
    }
    if (mat == 2) {
#pragma unroll
        for (int u = 0; u < 8; u++) {
            __half h = __float2half_rn(acc[u]);
            __half l = __float2half_rn(acc[u] - __half2float(h));
            size_t o = ((size_t)b * CH + o0 + u) * NPOS + pos;
            g_vh[o] = h;
            g_vl[o] = l;
        }
    } else {
        __half* hi = (mat == 0) ? g_qh : g_kh;
        __half* lo = (mat == 0) ? g_ql : g_kl;
        size_t base = ((size_t)b * NPOS + pos) * CH + o0;
        __half h[8], l[8];
#pragma unroll
        for (int u = 0; u < 8; u++) {
            h[u] = __float2half_rn(acc[u]);
            l[u] = __float2half_rn(acc[u] - __half2float(h[u]));
        }
        *(uint4*)&hi[base] = *(uint4*)h;
        *(uint4*)&lo[base] = *(uint4*)l;
    }
}

// ================= K2: scores via mma.sync fp16 2-split (3 products) =================
// grid (32 jt, 32 it, NB), block 256 (8 warps: 2 i x 4 j).
#define SU 36                        // u32 row stride (conflict-free: 36 mod 32 = 4)
#define SC_SMEM (4 * 128 * SU * 4)
__global__ void __launch_bounds__(256) scores_kernel()
{
    extern __shared__ u32 smu[];
    u32* sKhi = smu;
    u32* sKlo = smu + 128 * SU;
    u32* sQhi = smu + 2 * 128 * SU;
    u32* sQlo = smu + 3 * 128 * SU;

    int b  = blockIdx.z;
    int i0 = blockIdx.y * 128;
    int j0 = blockIdx.x * 128;
    int tid = threadIdx.x, wid = tid >> 5, lane = tid & 31;
    int gid = lane >> 2, ctid = lane & 3;
    int warp_i = wid >> 2;                 // 0..1
    int warp_j = wid & 3;                  // 0..3
    int ibase = warp_i * 64, jbase = warp_j * 32;

    // stage 4 fp16 tiles (128 rows x 64 c = 8 uint4/row)
    {
        const uint4* khi = (const uint4*)(g_kh + ((size_t)b * NPOS + i0) * CH);
        const uint4* klo = (const uint4*)(g_kl + ((size_t)b * NPOS + i0) * CH);
        const uint4* qhi = (const uint4*)(g_qh + ((size_t)b * NPOS + j0) * CH);
        const uint4* qlo = (const uint4*)(g_ql + ((size_t)b * NPOS + j0) * CH);
        for (int idx = tid; idx < 1024; idx += 256) {
            int row = idx >> 3, q4 = (idx & 7) * 4;
            *(uint4*)&sKhi[row * SU + q4] = khi[idx];
            *(uint4*)&sKlo[row * SU + q4] = klo[idx];
            *(uint4*)&sQhi[row * SU + q4] = qhi[idx];
            *(uint4*)&sQlo[row * SU + q4] = qlo[idx];
        }
    }
    __syncthreads();

    float cfr[4][4][4];
#pragma unroll
    for (int ti = 0; ti < 4; ti++)
#pragma unroll
        for (int tj = 0; tj < 4; tj++)
#pragma unroll
            for (int r = 0; r < 4; r++) cfr[ti][tj][r] = 0.f;

#pragma unroll
    for (int kk = 0; kk < 4; kk++) {
        int kc = kk * 8 + ctid;
        u32 ahi[4][4], alo[4][4];
#pragma unroll
        for (int ti = 0; ti < 4; ti++) {
            int r0 = (ibase + ti * 16 + gid) * SU + kc;
            int r1 = r0 + 8 * SU;
            ahi[ti][0] = sKhi[r0]; ahi[ti][1] = sKhi[r1];
            ahi[ti][2] = sKhi[r0 + 4]; ahi[ti][3] = sKhi[r1 + 4];
            alo[ti][0] = sKlo[r0]; alo[ti][1] = sKlo[r1];
            alo[ti][2] = sKlo[r0 + 4]; alo[ti][3] = sKlo[r1 + 4];
        }
        u32 bhi[4][2], blo[4][2];
#pragma unroll
        for (int tj = 0; tj < 4; tj++) {
            int c0 = (jbase + tj * 8 + gid) * SU + kc;
            bhi[tj][0] = sQhi[c0]; bhi[tj][1] = sQhi[c0 + 4];
            blo[tj][0] = sQlo[c0]; blo[tj][1] = sQlo[c0 + 4];
        }
#pragma unroll
        for (int ti = 0; ti < 4; ti++)
#pragma unroll
            for (int tj = 0; tj < 4; tj++) {
                mma_f16(cfr[ti][tj], ahi[ti][0], ahi[ti][1], ahi[ti][2], ahi[ti][3],
                        bhi[tj][0], bhi[tj][1]);
                mma_f16(cfr[ti][tj], ahi[ti][0], ahi[ti][1], ahi[ti][2], ahi[ti][3],
                        blo[tj][0], blo[tj][1]);
                mma_f16(cfr[ti][tj], alo[ti][0], alo[ti][1], alo[ti][2], alo[ti][3],
                        bhi[tj][0], bhi[tj][1]);
            }
    }

    // ---- stats per 32-col block + write P_loc = exp(S - m_b) as fp16 ----
    int jb = blockIdx.x * 4 + warp_j;
    __half* Pb = g_P + (size_t)b * NPOS * NPOS;
#pragma unroll
    for (int ti = 0; ti < 4; ti++) {
        float m0 = -1e30f, m1 = -1e30f;
#pragma unroll
        for (int tj = 0; tj < 4; tj++) {
            m0 = fmaxf(m0, fmaxf(cfr[ti][tj][0], cfr[ti][tj][1]));
            m1 = fmaxf(m1, fmaxf(cfr[ti][tj][2], cfr[ti][tj][3]));
        }
#pragma unroll
        for (int o = 1; o < 4; o <<= 1) {
            m0 = fmaxf(m0, __shfl_xor_sync(0xffffffffu, m0, o));
            m1 = fmaxf(m1, __shfl_xor_sync(0xffffffffu, m1, o));
        }
        int row0 = i0 + ibase + ti * 16 + gid;
        float s0 = 0.f, s1 = 0.f;
#pragma unroll
        for (int tj = 0; tj < 4; tj++) {
            float p00 = __expf(cfr[ti][tj][0] - m0);
            float p01 = __expf(cfr[ti][tj][1] - m0);
            float p10 = __expf(cfr[ti][tj][2] - m1);
            float p11 = __expf(cfr[ti][tj][3] - m1);
            s0 += p00 + p01;
            s1 += p10 + p11;
            int col = j0 + jbase + tj * 8 + 2 * ctid;
            *(__half2*)&Pb[(size_t)row0 * NPOS + col]       = __floats2half2_rn(p00, p01);
            *(__half2*)&Pb[(size_t)(row0 + 8) * NPOS + col] = __floats2half2_rn(p10, p11);
        }
#pragma unroll
        for (int o = 1; o < 4; o <<= 1) {
            s0 += __shfl_xor_sync(0xffffffffu, s0, o);
            s1 += __shfl_xor_sync(0xffffffffu, s1, o);
        }
        if (ctid == 0) {
            size_t sbase = ((size_t)b * JB + jb) * NPOS;
            g_mpart[sbase + row0]     = m0;
            g_spart[sbase + row0]     = s0;
            g_mpart[sbase + row0 + 8] = m1;
            g_spart[sbase + row0 + 8] = s1;
        }
    }
}

// ================= K3: combine stats =================
__global__ void __launch_bounds__(256) combine_kernel()
{
    int e = blockIdx.x * 256 + threadIdx.x;
    if (e >= NB * NPOS) return;
    int b = e / NPOS, i = e % NPOS;
    const float* mp = g_mpart + (size_t)b * JB * NPOS + i;
    const float* sp = g_spart + (size_t)b * JB * NPOS + i;
    float m = -1e30f;
#pragma unroll 8
    for (int jb = 0; jb < JB; jb++) m = fmaxf(m, mp[(size_t)jb * NPOS]);
    float s = 0.f;
#pragma unroll 8
    for (int jb = 0; jb < JB; jb++)
        s += __expf(mp[(size_t)jb * NPOS] - m) * sp[(size_t)jb * NPOS];
    g_m[e] = m;
    g_w[e] = 1.f / s;
}

// ================= K4: agg via mma.sync fp16 (V 2-split), P fp16 rescaled =================
// out[c][j] = sum_i V[c][i] * f[i,jb] * P_loc[i][j];  M=64 c, N=128 j, K=i chunks of 64.
// grid (32 jt, ASPLIT, NB), block 256 (8 warps: 2 c x 4 j).
#define AU 36
#define AG_VLO (64 * AU)
#define AG_PT  (2 * 64 * AU)
#define AG_F   (2 * 64 * AU + 128 * AU)
#define AG_SMEM ((AG_F + 256) * 4)
__global__ void __launch_bounds__(256) agg_kernel()
{
    extern __shared__ u32 smu[];
    u32* sVhi = smu;                   // [64 c][36]
    u32* sVlo = smu + AG_VLO;
    u32* sPT  = smu + AG_PT;           // [128 j][36]  (i-major fp16, stride 72 halves)
    float* sF = (float*)(smu + AG_F);  // [64 i][4 sub]

    int b  = blockIdx.z;
    int ks = blockIdx.y;
    int j0 = blockIdx.x * 128;
    const int IRANGE = NPOS / ASPLIT;       // 512
    int ibase_g = ks * IRANGE;

    int tid = threadIdx.x, wid = tid >> 5, lane = tid & 31;
    int gid = lane >> 2, ctid = lane & 3;
    int warp_c = wid >> 2;                  // 0..1
    int warp_j = wid & 3;                   // 0..3
    int cbase = warp_c * 32, jbase = warp_j * 32;

    const u32* vh = (const u32*)(g_vh + (size_t)b * CH * NPOS);
    const u32* vl = (const u32*)(g_vl + (size_t)b * CH * NPOS);
    const u32* Pu = (const u32*)(g_P + (size_t)b * NPOS * NPOS);

    float cfr[2][4][4];
#pragma unroll
    for (int ti = 0; ti < 2; ti++)
#pragma unroll
        for (int tj = 0; tj < 4; tj++)
#pragma unroll
            for (int r = 0; r < 4; r++) cfr[ti][tj][r] = 0.f;

#pragma unroll 1
    for (int ck = 0; ck < IRANGE / 64; ck++) {
        int i0 = ibase_g + ck * 64;
        __syncthreads();
        // f[i][sub]: 256 values
        {
            int ii = tid >> 2, sub = tid & 3;
            int jb = blockIdx.x * 4 + sub;
            float mb = g_mpart[((size_t)b * JB + jb) * NPOS + i0 + ii];
            sF[tid] = __expf(mb - g_m[b * NPOS + i0 + ii]) * g_w[b * NPOS + i0 + ii];
        }
        // stage V hi/lo [64 c][64 i] = 2048 u32 each
        for (int idx = tid; idx < 2048; idx += 256) {
            int c = idx >> 5, cu = idx & 31;
            int gsrc = ((c * NPOS + i0) >> 1) + cu;
            sVhi[c * AU + cu] = vh[gsrc];
            sVlo[c * AU + cu] = vl[gsrc];
        }
        __syncthreads();
        // stage P transposed with scale: 64 i x 128 j = 4096 u32 reads
        {
            __half* hPT = (__half*)sPT;
            for (int idx = tid; idx < 4096; idx += 256) {
                int ii = idx >> 6, ju = idx & 63;
                u32 pv = Pu[(((size_t)(i0 + ii) * NPOS + j0) >> 1) + ju];
                float2 pf = __half22float2(*(__half2*)&pv);
                float f = sF[(ii << 2) | (ju >> 4)];
                __half2 ph = __floats2half2_rn(pf.x * f, pf.y * f);
                int j = 2 * ju;
                hPT[j * (2 * AU) + ii]       = __low2half(ph);
                hPT[(j + 1) * (2 * AU) + ii] = __high2half(ph);
            }
        }
        __syncthreads();

#pragma unroll
        for (int kk = 0; kk < 4; kk++) {
            int kc = kk * 8 + ctid;
            u32 ahi[2][4], alo[2][4];
#pragma unroll
            for (int ti = 0; ti < 2; ti++) {
                int r0 = (cbase + ti * 16 + gid) * AU + kc;
                int r1 = r0 + 8 * AU;
                ahi[ti][0] = sVhi[r0]; ahi[ti][1] = sVhi[r1];
                ahi[ti][2] = sVhi[r0 + 4]; ahi[ti][3] = sVhi[r1 + 4];
                alo[ti][0] = sVlo[r0]; alo[ti][1] = sVlo[r1];
                alo[ti][2] = sVlo[r0 + 4]; alo[ti][3] = sVlo[r1 + 4];
            }
            u32 bb[4][2];
#pragma unroll
            for (int tj = 0; tj < 4; tj++) {
                int n = (jbase + tj * 8 + gid) * AU + kc;
                bb[tj][0] = sPT[n];
                bb[tj][1] = sPT[n + 4];
            }
#pragma unroll
            for (int ti = 0; ti < 2; ti++)
#pragma unroll
                for (int tj = 0; tj < 4; tj++) {
                    mma_f16(cfr[ti][tj], ahi[ti][0], ahi[ti][1], ahi[ti][2], ahi[ti][3],
                            bb[tj][0], bb[tj][1]);
                    mma_f16(cfr[ti][tj], alo[ti][0], alo[ti][1], alo[ti][2], alo[ti][3],
                            bb[tj][0], bb[tj][1]);
                }
        }
    }

    float* ap = g_aggp[ks] + (size_t)b * CH * NPOS;
#pragma unroll
    for (int ti = 0; ti < 2; ti++) {
        int c0 = cbase + ti * 16 + gid;
#pragma unroll
        for (int tj = 0; tj < 4; tj++) {
            int col = j0 + jbase + tj * 8 + 2 * ctid;
            *(float2*)&ap[(size_t)c0 * NPOS + col] =
                make_float2(cfr[ti][tj][0], cfr[ti][tj][1]);
            *(float2*)&ap[(size_t)(c0 + 8) * NPOS + col] =
                make_float2(cfr[ti][tj][2], cfr[ti][tj][3]);
        }
    }
}

// ================= K4b: reduce split-K partials =================
__global__ void __launch_bounds__(256) agg_reduce_kernel()
{
    int e = blockIdx.x * 256 + threadIdx.x;
    if (e >= NB * CH * NPOS) return;
    float s = 0.f;
#pragma unroll
    for (int ks = 0; ks < ASPLIT; ks++) s += g_aggp[ks][e];
    g_agg[e] = s;
}

// ================= K5: out = Wpost * agg + x =================
__global__ void __launch_bounds__(128) post_kernel(
    const float* __restrict__ x,
    const float* __restrict__ Wpost,
    float* __restrict__ out)
{
    int b   = blockIdx.x;
    int pos = blockIdx.y * 128 + threadIdx.x;
    int o0  = blockIdx.z * 8;

    float acc[8];
#pragma unroll
    for (int u = 0; u < 8; u++) acc[u] = 0.f;
    const float* ap = g_agg + (size_t)b * CH * NPOS + pos;
#pragma unroll 4
    for (int c = 0; c < CH; c++) {
        float av = ap[(size_t)c * NPOS];
#pragma unroll
        for (int u = 0; u < 8; u++)
            acc[u] += Wpost[(o0 + u) * CH + c] * av;
    }
#pragma unroll
    for (int u = 0; u < 8; u++) {
        size_t o = ((size_t)b * CIN + o0 + u) * NPOS + pos;
        out[o] = acc[u] + x[o];
    }
}

// ================= launch =================
extern "C" void kernel_launch(void* const* d_in, const int* in_sizes, int n_in,
                              void* d_out, int out_size)
{
    const float* x     = (const float*)d_in[0];
    const float* Wq    = (const float*)d_in[1];
    const float* Wk    = (const float*)d_in[2];
    const float* Wv    = (const float*)d_in[3];
    const float* Wpost = (const float*)d_in[4];
    float* out = (float*)d_out;

    cudaFuncSetAttribute(scores_kernel, cudaFuncAttributeMaxDynamicSharedMemorySize, SC_SMEM);
    cudaFuncSetAttribute(agg_kernel,    cudaFuncAttributeMaxDynamicSharedMemorySize, AG_SMEM);

    qkv_kernel<<<dim3(NB, NPOS / 128, 24), 128>>>(x, Wq, Wk, Wv);
    scores_kernel<<<dim3(NPOS / 128, NPOS / 128, NB), 256, SC_SMEM>>>();
    combine_kernel<<<(NB * NPOS + 255) / 256, 256>>>();
    agg_kernel<<<dim3(NPOS / 128, ASPLIT, NB), 256, AG_SMEM>>>();
    agg_reduce_kernel<<<(NB * CH * NPOS + 255) / 256, 256>>>();
    post_kernel<<<dim3(NB, NPOS / 128, 16), 128>>>(x, Wpost, out);
}

// round 9
// speedup vs baseline: 1.6481x; 1.0654x over previous
#include <cuda_runtime.h>
#include <cuda_fp16.h>
#include <cstdint>

#define NB   2
#define CIN  128
#define CH   64
#define NPOS 4096
#define JB   128          // 32-wide stat blocks
#define ASPLIT 4

typedef uint32_t u32;

// ================= helpers =================
__device__ __forceinline__ void mma_f16(float c[4], u32 a0, u32 a1, u32 a2, u32 a3,
                                        u32 b0, u32 b1) {
    asm volatile("mma.sync.aligned.m16n8k16.row.col.f32.f16.f16.f32 "
                 "{%0,%1,%2,%3}, {%4,%5,%6,%7}, {%8,%9}, {%0,%1,%2,%3};"
                 : "+f"(c[0]), "+f"(c[1]), "+f"(c[2]), "+f"(c[3])
                 : "r"(a0), "r"(a1), "r"(a2), "r"(a3), "r"(b0), "r"(b1));
}
__device__ __forceinline__ u32 smaddr(const void* p) {
    return (u32)__cvta_generic_to_shared(p);
}
#define LDSM_X4(r0, r1, r2, r3, a) \
    asm volatile("ldmatrix.sync.aligned.m8n8.x4.shared.b16 {%0,%1,%2,%3}, [%4];" \
        : "=r"(r0), "=r"(r1), "=r"(r2), "=r"(r3) : "r"(a))
#define LDSM_X2(r0, r1, a) \
    asm volatile("ldmatrix.sync.aligned.m8n8.x2.shared.b16 {%0,%1}, [%2];" \
        : "=r"(r0), "=r"(r1) : "r"(a))
#define LDSM_X2T(r0, r1, a) \
    asm volatile("ldmatrix.sync.aligned.m8n8.x2.trans.shared.b16 {%0,%1}, [%2];" \
        : "=r"(r0), "=r"(r1) : "r"(a))

// ================= scratch =================
__device__ __half g_kh[NB * NPOS * CH];     // [b][i][c]
__device__ __half g_kl[NB * NPOS * CH];
__device__ __half g_qh[NB * NPOS * CH];     // [b][j][c]
__device__ __half g_ql[NB * NPOS * CH];
__device__ __half g_vh[NB * CH * NPOS];     // [b][c][i]
__device__ __half g_vl[NB * CH * NPOS];
__device__ __half g_P [(size_t)NB * NPOS * NPOS];   // P_loc = exp(S - m_block)
__device__ float g_mpart[NB * JB * NPOS];
__device__ float g_spart[NB * JB * NPOS];
__device__ float g_m[NB * NPOS];
__device__ float g_w[NB * NPOS];
__device__ float g_aggp[ASPLIT][NB * CH * NPOS];
__device__ float g_agg[NB * CH * NPOS];

// ================= K1: qkv (fp16 hi/lo split) =================
__global__ void __launch_bounds__(128) qkv_kernel(
    const float* __restrict__ x,
    const float* __restrict__ Wq,
    const float* __restrict__ Wk,
    const float* __restrict__ Wv)
{
    int b   = blockIdx.x;
    int pos = blockIdx.y * 128 + threadIdx.x;
    int z   = blockIdx.z;            // 0..23
    int mat = z >> 3;
    int o0  = (z & 7) * 8;
    const float* W = (mat == 0) ? Wq : (mat == 1) ? Wk : Wv;

    float acc[8];
#pragma unroll
    for (int u = 0; u < 8; u++) acc[u] = 0.f;
    const float* xp = x + (size_t)b * CIN * NPOS + pos;
#pragma unroll 4
    for (int c = 0; c < CIN; c++) {
        float xv = xp[(size_t)c * NPOS];
#pragma unroll
        for (int u = 0; u < 8; u++)
            acc[u] += W[(o0 + u) * CIN + c] * xv;
    }
    if (mat == 2) {
#pragma unroll
        for (int u = 0; u < 8; u++) {
            __half h = __float2half_rn(acc[u]);
            __half l = __float2half_rn(acc[u] - __half2float(h));
            size_t o = ((size_t)b * CH + o0 + u) * NPOS + pos;
            g_vh[o] = h;
            g_vl[o] = l;
        }
    } else {
        __half* hi = (mat == 0) ? g_qh : g_kh;
        __half* lo = (mat == 0) ? g_ql : g_kl;
        size_t base = ((size_t)b * NPOS + pos) * CH + o0;
        __half h[8], l[8];
#pragma unroll
        for (int u = 0; u < 8; u++) {
            h[u] = __float2half_rn(acc[u]);
            l[u] = __float2half_rn(acc[u] - __half2float(h[u]));
        }
        *(uint4*)&hi[base] = *(uint4*)h;
        *(uint4*)&lo[base] = *(uint4*)l;
    }
}

// ================= K2: scores via fp16 2-split + ldmatrix =================
// grid (32 jt, 32 it, NB), block 256 (8 warps: 2 i x 4 j).
#define SU 36                        // u32 row stride
#define SC_SMEM (4 * 128 * SU * 4)
__global__ void __launch_bounds__(256) scores_kernel()
{
    extern __shared__ u32 smu[];
    u32* sKhi = smu;
    u32* sKlo = smu + 128 * SU;
    u32* sQhi = smu + 2 * 128 * SU;
    u32* sQlo = smu + 3 * 128 * SU;

    int b  = blockIdx.z;
    int i0 = blockIdx.y * 128;
    int j0 = blockIdx.x * 128;
    int tid = threadIdx.x, wid = tid >> 5, lane = tid & 31;
    int gid = lane >> 2, ctid = lane & 3;
    int warp_i = wid >> 2;                 // 0..1
    int warp_j = wid & 3;                  // 0..3
    int ibase = warp_i * 64, jbase = warp_j * 32;

    // stage 4 fp16 tiles (128 rows x 64 c = 8 uint4/row)
    {
        const uint4* khi = (const uint4*)(g_kh + ((size_t)b * NPOS + i0) * CH);
        const uint4* klo = (const uint4*)(g_kl + ((size_t)b * NPOS + i0) * CH);
        const uint4* qhi = (const uint4*)(g_qh + ((size_t)b * NPOS + j0) * CH);
        const uint4* qlo = (const uint4*)(g_ql + ((size_t)b * NPOS + j0) * CH);
        for (int idx = tid; idx < 1024; idx += 256) {
            int row = idx >> 3, q4 = (idx & 7) * 4;
            *(uint4*)&sKhi[row * SU + q4] = khi[idx];
            *(uint4*)&sKlo[row * SU + q4] = klo[idx];
            *(uint4*)&sQhi[row * SU + q4] = qhi[idx];
            *(uint4*)&sQlo[row * SU + q4] = qlo[idx];
        }
    }
    __syncthreads();

    // ldmatrix lane addresses (bytes)
    int arow = (lane & 7) + ((lane >> 3) & 1) * 8;      // A: x4
    int acol = (lane >> 4) * 4;                         // u32
    int brow = lane & 7;                                // B: x2 (lanes 0-15)
    int bcol = ((lane >> 3) & 1) * 4;
    u32 aKhi = smaddr(sKhi) + (u32)(((ibase + arow) * SU + acol) * 4);
    u32 aKlo = aKhi + 128 * SU * 4;
    u32 aQhi = smaddr(sQhi) + (u32)(((jbase + brow) * SU + bcol) * 4);
    u32 aQlo = aQhi + 128 * SU * 4;

    float cfr[4][4][4];
#pragma unroll
    for (int ti = 0; ti < 4; ti++)
#pragma unroll
        for (int tj = 0; tj < 4; tj++)
#pragma unroll
            for (int r = 0; r < 4; r++) cfr[ti][tj][r] = 0.f;

#pragma unroll
    for (int kk = 0; kk < 4; kk++) {
        u32 ahi[4][4], alo[4][4];
#pragma unroll
        for (int ti = 0; ti < 4; ti++) {
            u32 off = (u32)(ti * 16 * SU * 4 + kk * 32);
            LDSM_X4(ahi[ti][0], ahi[ti][1], ahi[ti][2], ahi[ti][3], aKhi + off);
            LDSM_X4(alo[ti][0], alo[ti][1], alo[ti][2], alo[ti][3], aKlo + off);
        }
        u32 bhi[4][2], blo[4][2];
#pragma unroll
        for (int tj = 0; tj < 4; tj++) {
            u32 off = (u32)(tj * 8 * SU * 4 + kk * 32);
            LDSM_X2(bhi[tj][0], bhi[tj][1], aQhi + off);
            LDSM_X2(blo[tj][0], blo[tj][1], aQlo + off);
        }
#pragma unroll
        for (int ti = 0; ti < 4; ti++)
#pragma unroll
            for (int tj = 0; tj < 4; tj++) {
                mma_f16(cfr[ti][tj], ahi[ti][0], ahi[ti][1], ahi[ti][2], ahi[ti][3],
                        bhi[tj][0], bhi[tj][1]);
                mma_f16(cfr[ti][tj], ahi[ti][0], ahi[ti][1], ahi[ti][2], ahi[ti][3],
                        blo[tj][0], blo[tj][1]);
                mma_f16(cfr[ti][tj], alo[ti][0], alo[ti][1], alo[ti][2], alo[ti][3],
                        bhi[tj][0], bhi[tj][1]);
            }
    }

    // ---- stats per 32-col block + write P_loc = exp(S - m_b) as fp16 ----
    int jb = blockIdx.x * 4 + warp_j;
    __half* Pb = g_P + (size_t)b * NPOS * NPOS;
#pragma unroll
    for (int ti = 0; ti < 4; ti++) {
        float m0 = -1e30f, m1 = -1e30f;
#pragma unroll
        for (int tj = 0; tj < 4; tj++) {
            m0 = fmaxf(m0, fmaxf(cfr[ti][tj][0], cfr[ti][tj][1]));
            m1 = fmaxf(m1, fmaxf(cfr[ti][tj][2], cfr[ti][tj][3]));
        }
#pragma unroll
        for (int o = 1; o < 4; o <<= 1) {
            m0 = fmaxf(m0, __shfl_xor_sync(0xffffffffu, m0, o));
            m1 = fmaxf(m1, __shfl_xor_sync(0xffffffffu, m1, o));
        }
        int row0 = i0 + ibase + ti * 16 + gid;
        float s0 = 0.f, s1 = 0.f;
#pragma unroll
        for (int tj = 0; tj < 4; tj++) {
            float p00 = __expf(cfr[ti][tj][0] - m0);
            float p01 = __expf(cfr[ti][tj][1] - m0);
            float p10 = __expf(cfr[ti][tj][2] - m1);
            float p11 = __expf(cfr[ti][tj][3] - m1);
            s0 += p00 + p01;
            s1 += p10 + p11;
            int col = j0 + jbase + tj * 8 + 2 * ctid;
            *(__half2*)&Pb[(size_t)row0 * NPOS + col]       = __floats2half2_rn(p00, p01);
            *(__half2*)&Pb[(size_t)(row0 + 8) * NPOS + col] = __floats2half2_rn(p10, p11);
        }
#pragma unroll
        for (int o = 1; o < 4; o <<= 1) {
            s0 += __shfl_xor_sync(0xffffffffu, s0, o);
            s1 += __shfl_xor_sync(0xffffffffu, s1, o);
        }
        if (ctid == 0) {
            size_t sbase = ((size_t)b * JB + jb) * NPOS;
            g_mpart[sbase + row0]     = m0;
            g_spart[sbase + row0]     = s0;
            g_mpart[sbase + row0 + 8] = m1;
            g_spart[sbase + row0 + 8] = s1;
        }
    }
}

// ================= K3: combine stats =================
__global__ void __launch_bounds__(256) combine_kernel()
{
    int e = blockIdx.x * 256 + threadIdx.x;
    if (e >= NB * NPOS) return;
    int b = e / NPOS, i = e % NPOS;
    const float* mp = g_mpart + (size_t)b * JB * NPOS + i;
    const float* sp = g_spart + (size_t)b * JB * NPOS + i;
    float m = -1e30f;
#pragma unroll 8
    for (int jb = 0; jb < JB; jb++) m = fmaxf(m, mp[(size_t)jb * NPOS]);
    float s = 0.f;
#pragma unroll 8
    for (int jb = 0; jb < JB; jb++)
        s += __expf(mp[(size_t)jb * NPOS] - m) * sp[(size_t)jb * NPOS];
    g_m[e] = m;
    g_w[e] = 1.f / s;
}

// ================= K4: agg, fp16 mma, natural-layout P + ldmatrix.trans =================
// out[c][j] = sum_i V[c][i] * f[i,jb] * P_loc[i][j];  M=64 c, N=128 j, K chunks of 64.
// grid (32 jt, ASPLIT, NB), block 256 (8 warps: 2 c x 4 j).
#define AU 36
#define PST 136                      // half stride of sP rows
#define AG_VLO (64 * AU)
#define AG_PT  (2 * 64 * AU)         // u32 offset of sP (64 * 68 u32)
#define AG_F   (2 * 64 * AU + 64 * (PST / 2))
#define AG_SMEM ((AG_F + 256) * 4)
__global__ void __launch_bounds__(256) agg_kernel()
{
    extern __shared__ u32 smu[];
    u32* sVhi = smu;                   // [64 c][36]
    u32* sVlo = smu + AG_VLO;
    __half* sPh = (__half*)(smu + AG_PT);  // [64 i][136]
    float* sF = (float*)(smu + AG_F);  // [64 i][4 sub]

    int b  = blockIdx.z;
    int ks = blockIdx.y;
    int j0 = blockIdx.x * 128;
    const int IRANGE = NPOS / ASPLIT;       // 1024
    int ibase_g = ks * IRANGE;

    int tid = threadIdx.x, wid = tid >> 5, lane = tid & 31;
    int gid = lane >> 2, ctid = lane & 3;
    int warp_c = wid >> 2;                  // 0..1
    int warp_j = wid & 3;                   // 0..3
    int cbase = warp_c * 32, jbase = warp_j * 32;

    const u32* vh = (const u32*)(g_vh + (size_t)b * CH * NPOS);
    const u32* vl = (const u32*)(g_vl + (size_t)b * CH * NPOS);
    const __half* Pb = g_P + (size_t)b * NPOS * NPOS;

    // ldmatrix lane addresses
    int arow = (lane & 7) + ((lane >> 3) & 1) * 8;
    int acol = (lane >> 4) * 4;
    u32 aVhi = smaddr(sVhi) + (u32)(((cbase + arow) * AU + acol) * 4);
    u32 aVlo = aVhi + AG_VLO * 4;
    int brow = lane & 15;                   // i row within 16-deep k chunk
    u32 aP = smaddr(sPh) + (u32)((brow * PST + jbase) * 2);

    float cfr[2][4][4];
#pragma unroll
    for (int ti = 0; ti < 2; ti++)
#pragma unroll
        for (int tj = 0; tj < 4; tj++)
#pragma unroll
            for (int r = 0; r < 4; r++) cfr[ti][tj][r] = 0.f;

#pragma unroll 1
    for (int ck = 0; ck < IRANGE / 64; ck++) {
        int i0 = ibase_g + ck * 64;
        __syncthreads();
        // f[i][sub]
        {
            int ii = tid >> 2, sub = tid & 3;
            int jb = blockIdx.x * 4 + sub;
            float mb = g_mpart[((size_t)b * JB + jb) * NPOS + i0 + ii];
            sF[tid] = __expf(mb - g_m[b * NPOS + i0 + ii]) * g_w[b * NPOS + i0 + ii];
        }
        // stage V hi/lo [64 c][64 i] = 2048 u32 each
        for (int idx = tid; idx < 2048; idx += 256) {
            int c = idx >> 5, cu = idx & 31;
            int gsrc = ((c * NPOS + i0) >> 1) + cu;
            sVhi[c * AU + cu] = vh[gsrc];
            sVlo[c * AU + cu] = vl[gsrc];
        }
        __syncthreads();
        // stage P naturally [64 i][128 j] with fp16 rescale: 1024 uint4
        for (int idx = tid; idx < 1024; idx += 256) {
            int ii = idx >> 4, j16 = idx & 15;
            uint4 pv = *(const uint4*)(Pb + (size_t)(i0 + ii) * NPOS + j0 + j16 * 8);
            float f = sF[(ii << 2) | (j16 >> 2)];
            __half2 f2 = __half2half2(__float2half_rn(f));
            __half2* ph = (__half2*)&pv;
            ph[0] = __hmul2(ph[0], f2);
            ph[1] = __hmul2(ph[1], f2);
            ph[2] = __hmul2(ph[2], f2);
            ph[3] = __hmul2(ph[3], f2);
            *(uint4*)(sPh + ii * PST + j16 * 8) = pv;
        }
        __syncthreads();

#pragma unroll
        for (int kk = 0; kk < 4; kk++) {
            u32 ahi[2][4], alo[2][4];
#pragma unroll
            for (int ti = 0; ti < 2; ti++) {
                u32 off = (u32)(ti * 16 * AU * 4 + kk * 32);
                LDSM_X4(ahi[ti][0], ahi[ti][1], ahi[ti][2], ahi[ti][3], aVhi + off);
                LDSM_X4(alo[ti][0], alo[ti][1], alo[ti][2], alo[ti][3], aVlo + off);
            }
            u32 bb[4][2];
#pragma unroll
            for (int tj = 0; tj < 4; tj++) {
                u32 off = (u32)(kk * 16 * PST * 2 + tj * 16);
                LDSM_X2T(bb[tj][0], bb[tj][1], aP + off);
            }
#pragma unroll
            for (int ti = 0; ti < 2; ti++)
#pragma unroll
                for (int tj = 0; tj < 4; tj++) {
                    mma_f16(cfr[ti][tj], ahi[ti][0], ahi[ti][1], ahi[ti][2], ahi[ti][3],
                            bb[tj][0], bb[tj][1]);
                    mma_f16(cfr[ti][tj], alo[ti][0], alo[ti][1], alo[ti][2], alo[ti][3],
                            bb[tj][0], bb[tj][1]);
                }
        }
    }

    float* ap = g_aggp[ks] + (size_t)b * CH * NPOS;
#pragma unroll
    for (int ti = 0; ti < 2; ti++) {
        int c0 = cbase + ti * 16 + gid;
#pragma unroll
        for (int tj = 0; tj < 4; tj++) {
            int col = j0 + jbase + tj * 8 + 2 * ctid;
            *(float2*)&ap[(size_t)c0 * NPOS + col] =
                make_float2(cfr[ti][tj][0], cfr[ti][tj][1]);
            *(float2*)&ap[(size_t)(c0 + 8) * NPOS + col] =
                make_float2(cfr[ti][tj][2], cfr[ti][tj][3]);
        }
    }
}

// ================= K4b: reduce split-K partials =================
__global__ void __launch_bounds__(256) agg_reduce_kernel()
{
    int e = blockIdx.x * 256 + threadIdx.x;
    if (e >= NB * CH * NPOS) return;
    float s = 0.f;
#pragma unroll
    for (int ks = 0; ks < ASPLIT; ks++) s += g_aggp[ks][e];
    g_agg[e] = s;
}

// ================= K5: out = Wpost * agg + x =================
__global__ void __launch_bounds__(128) post_kernel(
    const float* __restrict__ x,
    const float* __restrict__ Wpost,
    float* __restrict__ out)
{
    int b   = blockIdx.x;
    int pos = blockIdx.y * 128 + threadIdx.x;
    int o0  = blockIdx.z * 8;

    float acc[8];
#pragma unroll
    for (int u = 0; u < 8; u++) acc[u] = 0.f;
    const float* ap = g_agg + (size_t)b * CH * NPOS + pos;
#pragma unroll 4
    for (int c = 0; c < CH; c++) {
        float av = ap[(size_t)c * NPOS];
#pragma unroll
        for (int u = 0; u < 8; u++)
            acc[u] += Wpost[(o0 + u) * CH + c] * av;
    }
#pragma unroll
    for (int u = 0; u < 8; u++) {
        size_t o = ((size_t)b * CIN + o0 + u) * NPOS + pos;
        out[o] = acc[u] + x[o];
    }
}

// ================= launch =================
extern "C" void kernel_launch(void* const* d_in, const int* in_sizes, int n_in,
                              void* d_out, int out_size)
{
    const float* x     = (const float*)d_in[0];
    const float* Wq    = (const float*)d_in[1];
    const float* Wk    = (const float*)d_in[2];
    const float* Wv    = (const float*)d_in[3];
    const float* Wpost = (const float*)d_in[4];
    float* out = (float*)d_out;

    cudaFuncSetAttribute(scores_kernel, cudaFuncAttributeMaxDynamicSharedMemorySize, SC_SMEM);
    cudaFuncSetAttribute(agg_kernel,    cudaFuncAttributeMaxDynamicSharedMemorySize, AG_SMEM);

    qkv_kernel<<<dim3(NB, NPOS / 128, 24), 128>>>(x, Wq, Wk, Wv);
    scores_kernel<<<dim3(NPOS / 128, NPOS / 128, NB), 256, SC_SMEM>>>();
    combine_kernel<<<(NB * NPOS + 255) / 256, 256>>>();
    agg_kernel<<<dim3(NPOS / 128, ASPLIT, NB), 256, AG_SMEM>>>();
    agg_reduce_kernel<<<(NB * CH * NPOS + 255) / 256, 256>>>();
    post_kernel<<<dim3(NB, NPOS / 128, 16), 128>>>(x, Wpost, out);
}

// round 10
// speedup vs baseline: 1.9198x; 1.1648x over previous
#include <cuda_runtime.h>
#include <cuda_fp16.h>
#include <cstdint>

#define NB   2
#define CIN  128
#define CH   64
#define NPOS 4096
#define JB   128          // 32-wide stat blocks
#define ASPLIT 8

typedef uint32_t u32;

// ================= helpers =================
__device__ __forceinline__ void mma_f16(float c[4], u32 a0, u32 a1, u32 a2, u32 a3,
                                        u32 b0, u32 b1) {
    asm volatile("mma.sync.aligned.m16n8k16.row.col.f32.f16.f16.f32 "
                 "{%0,%1,%2,%3}, {%4,%5,%6,%7}, {%8,%9}, {%0,%1,%2,%3};"
                 : "+f"(c[0]), "+f"(c[1]), "+f"(c[2]), "+f"(c[3])
                 : "r"(a0), "r"(a1), "r"(a2), "r"(a3), "r"(b0), "r"(b1));
}
__device__ __forceinline__ u32 smaddr(const void* p) {
    return (u32)__cvta_generic_to_shared(p);
}
#define LDSM_X4(r0, r1, r2, r3, a) \
    asm volatile("ldmatrix.sync.aligned.m8n8.x4.shared.b16 {%0,%1,%2,%3}, [%4];" \
        : "=r"(r0), "=r"(r1), "=r"(r2), "=r"(r3) : "r"(a))
#define LDSM_X2(r0, r1, a) \
    asm volatile("ldmatrix.sync.aligned.m8n8.x2.shared.b16 {%0,%1}, [%2];" \
        : "=r"(r0), "=r"(r1) : "r"(a))
#define LDSM_X2T(r0, r1, a) \
    asm volatile("ldmatrix.sync.aligned.m8n8.x2.trans.shared.b16 {%0,%1}, [%2];" \
        : "=r"(r0), "=r"(r1) : "r"(a))

// ================= scratch =================
__device__ __half g_kh[NB * NPOS * CH];     // [b][i][c]
__device__ __half g_kl[NB * NPOS * CH];
__device__ __half g_qh[NB * NPOS * CH];     // [b][j][c]
__device__ __half g_ql[NB * NPOS * CH];
__device__ __half g_vh[NB * CH * NPOS];     // [b][c][i]
__device__ __half g_vl[NB * CH * NPOS];
__device__ __half g_P [(size_t)NB * NPOS * NPOS];   // P_loc = exp(S - m_block)
__device__ float g_mpart[NB * JB * NPOS];
__device__ float g_spart[NB * JB * NPOS];
__device__ float g_m[NB * NPOS];
__device__ float g_w[NB * NPOS];
__device__ float g_aggp[ASPLIT][NB * CH * NPOS];
__device__ float g_agg[NB * CH * NPOS];

// ================= K1: qkv (fp16 hi/lo split) =================
__global__ void __launch_bounds__(128) qkv_kernel(
    const float* __restrict__ x,
    const float* __restrict__ Wq,
    const float* __restrict__ Wk,
    const float* __restrict__ Wv)
{
    int b   = blockIdx.x;
    int pos = blockIdx.y * 128 + threadIdx.x;
    int z   = blockIdx.z;            // 0..23
    int mat = z >> 3;
    int o0  = (z & 7) * 8;
    const float* W = (mat == 0) ? Wq : (mat == 1) ? Wk : Wv;

    float acc[8];
#pragma unroll
    for (int u = 0; u < 8; u++) acc[u] = 0.f;
    const float* xp = x + (size_t)b * CIN * NPOS + pos;
#pragma unroll 4
    for (int c = 0; c < CIN; c++) {
        float xv = xp[(size_t)c * NPOS];
#pragma unroll
        for (int u = 0; u < 8; u++)
            acc[u] += W[(o0 + u) * CIN + c] * xv;
    }
    if (mat == 2) {
#pragma unroll
        for (int u = 0; u < 8; u++) {
            __half h = __float2half_rn(acc[u]);
            __half l = __float2half_rn(acc[u] - __half2float(h));
            size_t o = ((size_t)b * CH + o0 + u) * NPOS + pos;
            g_vh[o] = h;
            g_vl[o] = l;
        }
    } else {
        __half* hi = (mat == 0) ? g_qh : g_kh;
        __half* lo = (mat == 0) ? g_ql : g_kl;
        size_t base = ((size_t)b * NPOS + pos) * CH + o0;
        __half h[8], l[8];
#pragma unroll
        for (int u = 0; u < 8; u++) {
            h[u] = __float2half_rn(acc[u]);
            l[u] = __float2half_rn(acc[u] - __half2float(h[u]));
        }
        *(uint4*)&hi[base] = *(uint4*)h;
        *(uint4*)&lo[base] = *(uint4*)l;
    }
}

// ================= K2: scores via fp16 2-split + ldmatrix =================
// grid (32 jt, 32 it, NB), block 256 (8 warps: 2 i x 4 j).
#define SU 36                        // u32 row stride
#define SC_SMEM (4 * 128 * SU * 4)
__global__ void __launch_bounds__(256) scores_kernel()
{
    extern __shared__ u32 smu[];
    u32* sKhi = smu;
    u32* sKlo = smu + 128 * SU;
    u32* sQhi = smu + 2 * 128 * SU;
    u32* sQlo = smu + 3 * 128 * SU;

    int b  = blockIdx.z;
    int i0 = blockIdx.y * 128;
    int j0 = blockIdx.x * 128;
    int tid = threadIdx.x, wid = tid >> 5, lane = tid & 31;
    int gid = lane >> 2, ctid = lane & 3;
    int warp_i = wid >> 2;                 // 0..1
    int warp_j = wid & 3;                  // 0..3
    int ibase = warp_i * 64, jbase = warp_j * 32;

    // stage 4 fp16 tiles (128 rows x 64 c = 8 uint4/row)
    {
        const uint4* khi = (const uint4*)(g_kh + ((size_t)b * NPOS + i0) * CH);
        const uint4* klo = (const uint4*)(g_kl + ((size_t)b * NPOS + i0) * CH);
        const uint4* qhi = (const uint4*)(g_qh + ((size_t)b * NPOS + j0) * CH);
        const uint4* qlo = (const uint4*)(g_ql + ((size_t)b * NPOS + j0) * CH);
        for (int idx = tid; idx < 1024; idx += 256) {
            int row = idx >> 3, q4 = (idx & 7) * 4;
            *(uint4*)&sKhi[row * SU + q4] = khi[idx];
            *(uint4*)&sKlo[row * SU + q4] = klo[idx];
            *(uint4*)&sQhi[row * SU + q4] = qhi[idx];
            *(uint4*)&sQlo[row * SU + q4] = qlo[idx];
        }
    }
    __syncthreads();

    // ldmatrix lane addresses (bytes)
    int arow = (lane & 7) + ((lane >> 3) & 1) * 8;      // A: x4
    int acol = (lane >> 4) * 4;                         // u32
    int brow = lane & 7;                                // B: x2 (lanes 0-15)
    int bcol = ((lane >> 3) & 1) * 4;
    u32 aKhi = smaddr(sKhi) + (u32)(((ibase + arow) * SU + acol) * 4);
    u32 aKlo = aKhi + 128 * SU * 4;
    u32 aQhi = smaddr(sQhi) + (u32)(((jbase + brow) * SU + bcol) * 4);
    u32 aQlo = aQhi + 128 * SU * 4;

    float cfr[4][4][4];
#pragma unroll
    for (int ti = 0; ti < 4; ti++)
#pragma unroll
        for (int tj = 0; tj < 4; tj++)
#pragma unroll
            for (int r = 0; r < 4; r++) cfr[ti][tj][r] = 0.f;

#pragma unroll
    for (int kk = 0; kk < 4; kk++) {
        u32 ahi[4][4], alo[4][4];
#pragma unroll
        for (int ti = 0; ti < 4; ti++) {
            u32 off = (u32)(ti * 16 * SU * 4 + kk * 32);
            LDSM_X4(ahi[ti][0], ahi[ti][1], ahi[ti][2], ahi[ti][3], aKhi + off);
            LDSM_X4(alo[ti][0], alo[ti][1], alo[ti][2], alo[ti][3], aKlo + off);
        }
        u32 bhi[4][2], blo[4][2];
#pragma unroll
        for (int tj = 0; tj < 4; tj++) {
            u32 off = (u32)(tj * 8 * SU * 4 + kk * 32);
            LDSM_X2(bhi[tj][0], bhi[tj][1], aQhi + off);
            LDSM_X2(blo[tj][0], blo[tj][1], aQlo + off);
        }
#pragma unroll
        for (int ti = 0; ti < 4; ti++)
#pragma unroll
            for (int tj = 0; tj < 4; tj++) {
                mma_f16(cfr[ti][tj], ahi[ti][0], ahi[ti][1], ahi[ti][2], ahi[ti][3],
                        bhi[tj][0], bhi[tj][1]);
                mma_f16(cfr[ti][tj], ahi[ti][0], ahi[ti][1], ahi[ti][2], ahi[ti][3],
                        blo[tj][0], blo[tj][1]);
                mma_f16(cfr[ti][tj], alo[ti][0], alo[ti][1], alo[ti][2], alo[ti][3],
                        bhi[tj][0], bhi[tj][1]);
            }
    }

    // ---- stats per 32-col block + write P_loc = exp(S - m_b) as fp16 ----
    int jb = blockIdx.x * 4 + warp_j;
    __half* Pb = g_P + (size_t)b * NPOS * NPOS;
#pragma unroll
    for (int ti = 0; ti < 4; ti++) {
        float m0 = -1e30f, m1 = -1e30f;
#pragma unroll
        for (int tj = 0; tj < 4; tj++) {
            m0 = fmaxf(m0, fmaxf(cfr[ti][tj][0], cfr[ti][tj][1]));
            m1 = fmaxf(m1, fmaxf(cfr[ti][tj][2], cfr[ti][tj][3]));
        }
#pragma unroll
        for (int o = 1; o < 4; o <<= 1) {
            m0 = fmaxf(m0, __shfl_xor_sync(0xffffffffu, m0, o));
            m1 = fmaxf(m1, __shfl_xor_sync(0xffffffffu, m1, o));
        }
        int row0 = i0 + ibase + ti * 16 + gid;
        float s0 = 0.f, s1 = 0.f;
#pragma unroll
        for (int tj = 0; tj < 4; tj++) {
            float p00 = __expf(cfr[ti][tj][0] - m0);
            float p01 = __expf(cfr[ti][tj][1] - m0);
            float p10 = __expf(cfr[ti][tj][2] - m1);
            float p11 = __expf(cfr[ti][tj][3] - m1);
            s0 += p00 + p01;
            s1 += p10 + p11;
            int col = j0 + jbase + tj * 8 + 2 * ctid;
            *(__half2*)&Pb[(size_t)row0 * NPOS + col]       = __floats2half2_rn(p00, p01);
            *(__half2*)&Pb[(size_t)(row0 + 8) * NPOS + col] = __floats2half2_rn(p10, p11);
        }
#pragma unroll
        for (int o = 1; o < 4; o <<= 1) {
            s0 += __shfl_xor_sync(0xffffffffu, s0, o);
            s1 += __shfl_xor_sync(0xffffffffu, s1, o);
        }
        if (ctid == 0) {
            size_t sbase = ((size_t)b * JB + jb) * NPOS;
            g_mpart[sbase + row0]     = m0;
            g_spart[sbase + row0]     = s0;
            g_mpart[sbase + row0 + 8] = m1;
            g_spart[sbase + row0 + 8] = s1;
        }
    }
}

// ================= K3: combine stats =================
__global__ void __launch_bounds__(256) combine_kernel()
{
    int e = blockIdx.x * 256 + threadIdx.x;
    if (e >= NB * NPOS) return;
    int b = e / NPOS, i = e % NPOS;
    const float* mp = g_mpart + (size_t)b * JB * NPOS + i;
    const float* sp = g_spart + (size_t)b * JB * NPOS + i;
    float m = -1e30f;
#pragma unroll 8
    for (int jb = 0; jb < JB; jb++) m = fmaxf(m, mp[(size_t)jb * NPOS]);
    float s = 0.f;
#pragma unroll 8
    for (int jb = 0; jb < JB; jb++)
        s += __expf(mp[(size_t)jb * NPOS] - m) * sp[(size_t)jb * NPOS];
    g_m[e] = m;
    g_w[e] = 1.f / s;
}

// ================= K4: agg, fp16 mma, natural-layout P + ldmatrix.trans =================
// out[c][j] = sum_i V[c][i] * f[i,jb] * P_loc[i][j];  M=64 c, N=128 j, K chunks of 64.
// grid (32 jt, ASPLIT, NB), block 256 (8 warps: 2 c x 4 j).
#define AU 36
#define PST 136                      // half stride of sP rows
#define AG_VLO (64 * AU)
#define AG_PT  (2 * 64 * AU)         // u32 offset of sP
#define AG_F   (2 * 64 * AU + 64 * (PST / 2))
#define AG_SMEM ((AG_F + 256) * 4)
__global__ void __launch_bounds__(256) agg_kernel()
{
    extern __shared__ u32 smu[];
    u32* sVhi = smu;                   // [64 c][36]
    u32* sVlo = smu + AG_VLO;
    __half* sPh = (__half*)(smu + AG_PT);  // [64 i][136]
    float* sF = (float*)(smu + AG_F);  // [64 i][4 sub]

    int b  = blockIdx.z;
    int ks = blockIdx.y;
    int j0 = blockIdx.x * 128;
    const int IRANGE = NPOS / ASPLIT;       // 512
    int ibase_g = ks * IRANGE;

    int tid = threadIdx.x, wid = tid >> 5, lane = tid & 31;
    int gid = lane >> 2, ctid = lane & 3;
    int warp_c = wid >> 2;                  // 0..1
    int warp_j = wid & 3;                   // 0..3
    int cbase = warp_c * 32, jbase = warp_j * 32;

    const u32* vh = (const u32*)(g_vh + (size_t)b * CH * NPOS);
    const u32* vl = (const u32*)(g_vl + (size_t)b * CH * NPOS);
    const __half* Pb = g_P + (size_t)b * NPOS * NPOS;

    // ldmatrix lane addresses
    int arow = (lane & 7) + ((lane >> 3) & 1) * 8;
    int acol = (lane >> 4) * 4;
    u32 aVhi = smaddr(sVhi) + (u32)(((cbase + arow) * AU + acol) * 4);
    u32 aVlo = aVhi + AG_VLO * 4;
    int brow = lane & 15;                   // i row within 16-deep k chunk
    u32 aP = smaddr(sPh) + (u32)((brow * PST + jbase) * 2);

    float cfr[2][4][4];
#pragma unroll
    for (int ti = 0; ti < 2; ti++)
#pragma unroll
        for (int tj = 0; tj < 4; tj++)
#pragma unroll
            for (int r = 0; r < 4; r++) cfr[ti][tj][r] = 0.f;

#pragma unroll 1
    for (int ck = 0; ck < IRANGE / 64; ck++) {
        int i0 = ibase_g + ck * 64;
        __syncthreads();
        // f[i][sub]
        {
            int ii = tid >> 2, sub = tid & 3;
            int jb = blockIdx.x * 4 + sub;
            float mb = g_mpart[((size_t)b * JB + jb) * NPOS + i0 + ii];
            sF[tid] = __expf(mb - g_m[b * NPOS + i0 + ii]) * g_w[b * NPOS + i0 + ii];
        }
        // stage V hi/lo [64 c][64 i] = 2048 u32 each
        for (int idx = tid; idx < 2048; idx += 256) {
            int c = idx >> 5, cu = idx & 31;
            int gsrc = ((c * NPOS + i0) >> 1) + cu;
            sVhi[c * AU + cu] = vh[gsrc];
            sVlo[c * AU + cu] = vl[gsrc];
        }
        __syncthreads();
        // stage P naturally [64 i][128 j] with fp16 rescale: 1024 uint4
        for (int idx = tid; idx < 1024; idx += 256) {
            int ii = idx >> 4, j16 = idx & 15;
            uint4 pv = *(const uint4*)(Pb + (size_t)(i0 + ii) * NPOS + j0 + j16 * 8);
            float f = sF[(ii << 2) | (j16 >> 2)];
            __half2 f2 = __half2half2(__float2half_rn(f));
            __half2* ph = (__half2*)&pv;
            ph[0] = __hmul2(ph[0], f2);
            ph[1] = __hmul2(ph[1], f2);
            ph[2] = __hmul2(ph[2], f2);
            ph[3] = __hmul2(ph[3], f2);
            *(uint4*)(sPh + ii * PST + j16 * 8) = pv;
        }
        __syncthreads();

#pragma unroll
        for (int kk = 0; kk < 4; kk++) {
            u32 ahi[2][4], alo[2][4];
#pragma unroll
            for (int ti = 0; ti < 2; ti++) {
                u32 off = (u32)(ti * 16 * AU * 4 + kk * 32);
                LDSM_X4(ahi[ti][0], ahi[ti][1], ahi[ti][2], ahi[ti][3], aVhi + off);
                LDSM_X4(alo[ti][0], alo[ti][1], alo[ti][2], alo[ti][3], aVlo + off);
            }
            u32 bb[4][2];
#pragma unroll
            for (int tj = 0; tj < 4; tj++) {
                u32 off = (u32)(kk * 16 * PST * 2 + tj * 16);
                LDSM_X2T(bb[tj][0], bb[tj][1], aP + off);
            }
#pragma unroll
            for (int ti = 0; ti < 2; ti++)
#pragma unroll
                for (int tj = 0; tj < 4; tj++) {
                    mma_f16(cfr[ti][tj], ahi[ti][0], ahi[ti][1], ahi[ti][2], ahi[ti][3],
                            bb[tj][0], bb[tj][1]);
                    mma_f16(cfr[ti][tj], alo[ti][0], alo[ti][1], alo[ti][2], alo[ti][3],
                            bb[tj][0], bb[tj][1]);
                }
        }
    }

    float* ap = g_aggp[ks] + (size_t)b * CH * NPOS;
#pragma unroll
    for (int ti = 0; ti < 2; ti++) {
        int c0 = cbase + ti * 16 + gid;
#pragma unroll
        for (int tj = 0; tj < 4; tj++) {
            int col = j0 + jbase + tj * 8 + 2 * ctid;
            *(float2*)&ap[(size_t)c0 * NPOS + col] =
                make_float2(cfr[ti][tj][0], cfr[ti][tj][1]);
            *(float2*)&ap[(size_t)(c0 + 8) * NPOS + col] =
                make_float2(cfr[ti][tj][2], cfr[ti][tj][3]);
        }
    }
}

// ================= K4b: reduce split-K partials =================
__global__ void __launch_bounds__(256) agg_reduce_kernel()
{
    int e = blockIdx.x * 256 + threadIdx.x;
    if (e >= NB * CH * NPOS) return;
    float s = 0.f;
#pragma unroll
    for (int ks = 0; ks < ASPLIT; ks++) s += g_aggp[ks][e];
    g_agg[e] = s;
}

// ================= K5: out = Wpost * agg + x =================
__global__ void __launch_bounds__(128) post_kernel(
    const float* __restrict__ x,
    const float* __restrict__ Wpost,
    float* __restrict__ out)
{
    int b   = blockIdx.x;
    int pos = blockIdx.y * 128 + threadIdx.x;
    int o0  = blockIdx.z * 8;

    float acc[8];
#pragma unroll
    for (int u = 0; u < 8; u++) acc[u] = 0.f;
    const float* ap = g_agg + (size_t)b * CH * NPOS + pos;
#pragma unroll 4
    for (int c = 0; c < CH; c++) {
        float av = ap[(size_t)c * NPOS];
#pragma unroll
        for (int u = 0; u < 8; u++)
            acc[u] += Wpost[(o0 + u) * CH + c] * av;
    }
#pragma unroll
    for (int u = 0; u < 8; u++) {
        size_t o = ((size_t)b * CIN + o0 + u) * NPOS + pos;
        out[o] = acc[u] + x[o];
    }
}

// ================= launch =================
extern "C" void kernel_launch(void* const* d_in, const int* in_sizes, int n_in,
                              void* d_out, int out_size)
{
    const float* x     = (const float*)d_in[0];
    const float* Wq    = (const float*)d_in[1];
    const float* Wk    = (const float*)d_in[2];
    const float* Wv    = (const float*)d_in[3];
    const float* Wpost = (const float*)d_in[4];
    float* out = (float*)d_out;

    cudaFuncSetAttribute(scores_kernel, cudaFuncAttributeMaxDynamicSharedMemorySize, SC_SMEM);
    cudaFuncSetAttribute(agg_kernel,    cudaFuncAttributeMaxDynamicSharedMemorySize, AG_SMEM);

    qkv_kernel<<<dim3(NB, NPOS / 128, 24), 128>>>(x, Wq, Wk, Wv);
    scores_kernel<<<dim3(NPOS / 128, NPOS / 128, NB), 256, SC_SMEM>>>();
    combine_kernel<<<(NB * NPOS + 255) / 256, 256>>>();
    agg_kernel<<<dim3(NPOS / 128, ASPLIT, NB), 256, AG_SMEM>>>();
    agg_reduce_kernel<<<(NB * CH * NPOS + 255) / 256, 256>>>();
    post_kernel<<<dim3(NB, NPOS / 128, 16), 128>>>(x, Wpost, out);
}